// round 3
// baseline (speedup 1.0000x reference)
#include <cuda_runtime.h>
#include <math.h>

#define B 32
#define C 256
#define HW 56
#define BC (B*C)
#define POOL 7
#define NN 64
#define HEADS 8
#define HD 32
#define EPS 1e-5f

// ---------------- scratch ----------------
__device__ float g_mean_h[BC * HW];
__device__ float g_mean_w[BC * HW];
__device__ float g_attn_h[BC * HW];
__device__ float g_attn_w[BC * HW];
__device__ float g_pooled[BC * NN];
__device__ float g_bsum[B];
__device__ float g_bsumsq[B];
__device__ float g_ca[BC];

// ---------------- kernel 1: row & col means of each 56x56 plane ------------
__global__ __launch_bounds__(256) void k_means(const float* __restrict__ x) {
    __shared__ float sp[HW][HW + 1];
    int bc = blockIdx.x, tid = threadIdx.x;
    if (tid == 0 && bc < B) { g_bsum[bc] = 0.f; g_bsumsq[bc] = 0.f; }
    const float4* xp = (const float4*)(x + (size_t)bc * HW * HW);
    #pragma unroll
    for (int k = 0; k < 4; ++k) {
        int f = tid + 256 * k;
        if (f < 784) {
            float4 v = xp[f];
            int r = f / 14, c = (f - r * 14) * 4;
            sp[r][c]     = v.x;
            sp[r][c + 1] = v.y;
            sp[r][c + 2] = v.z;
            sp[r][c + 3] = v.w;
        }
    }
    __syncthreads();
    // 4 threads per row: parallel row+col sums, shfl combine within lane-quads
    if (tid < 224) {
        int r = tid >> 2, sub = tid & 3;
        float rs = 0.f, cs = 0.f;
        #pragma unroll
        for (int w = 0; w < 14; ++w) {
            int idx = sub + 4 * w;
            rs += sp[r][idx];
            cs += sp[idx][r];
        }
        rs += __shfl_xor_sync(~0u, rs, 1); rs += __shfl_xor_sync(~0u, rs, 2);
        cs += __shfl_xor_sync(~0u, cs, 1); cs += __shfl_xor_sync(~0u, cs, 2);
        if (sub == 0) {
            g_mean_h[bc * HW + r] = rs * (1.f / 56.f);
            g_mean_w[bc * HW + r] = cs * (1.f / 56.f);
        }
    }
}

// ---------------- kernel 2: sa_branch (dwconv -> GN(4) -> sigmoid) ---------
__global__ __launch_bounds__(256) void k_sa(
    const float* __restrict__ w3, const float* __restrict__ b3,
    const float* __restrict__ w5, const float* __restrict__ b5,
    const float* __restrict__ w7, const float* __restrict__ b7,
    const float* __restrict__ w9, const float* __restrict__ b9,
    const float* __restrict__ sh, const float* __restrict__ bh,
    const float* __restrict__ sw, const float* __restrict__ bw)
{
    __shared__ float sin_[64 * HW];
    __shared__ float sy_[64 * HW];
    __shared__ float r1[8], r2[8], sstat[2];

    int g  = blockIdx.x;
    int b  = blockIdx.y;
    int br = blockIdx.z;
    const float* in  = (br == 0) ? g_mean_h : g_mean_w;
    float*       out = (br == 0) ? g_attn_h : g_attn_w;
    const float* sc  = (br == 0) ? sh : sw;
    const float* bi  = (br == 0) ? bh : bw;
    const float* wf; const float* bf; int ksz;
    if (g == 0)      { wf = w3; bf = b3; ksz = 3; }
    else if (g == 1) { wf = w5; bf = b5; ksz = 5; }
    else if (g == 2) { wf = w7; bf = b7; ksz = 7; }
    else             { wf = w9; bf = b9; ksz = 9; }
    int pad = ksz >> 1;

    int tid = threadIdx.x;
    size_t base = ((size_t)b * C + g * 64) * HW;
    for (int i = tid; i < 64 * HW; i += 256) sin_[i] = in[base + i];
    __syncthreads();

    float s = 0.f, ss = 0.f;
    for (int i = tid; i < 64 * HW; i += 256) {
        int c = i / HW, l = i - c * HW;
        float acc = bf[c];
        for (int j = 0; j < ksz; ++j) {
            int idx = l + j - pad;
            if (idx >= 0 && idx < HW) acc = fmaf(wf[c * ksz + j], sin_[c * HW + idx], acc);
        }
        sy_[i] = acc;
        s += acc; ss = fmaf(acc, acc, ss);
    }
    int lane = tid & 31, wid = tid >> 5;
    #pragma unroll
    for (int o = 16; o; o >>= 1) { s += __shfl_xor_sync(~0u, s, o); ss += __shfl_xor_sync(~0u, ss, o); }
    if (lane == 0) { r1[wid] = s; r2[wid] = ss; }
    __syncthreads();
    if (tid == 0) {
        float a = 0.f, bsum = 0.f;
        #pragma unroll
        for (int w = 0; w < 8; ++w) { a += r1[w]; bsum += r2[w]; }
        float mean = a * (1.f / 3584.f);
        float var  = bsum * (1.f / 3584.f) - mean * mean;
        sstat[0] = mean;
        sstat[1] = rsqrtf(var + EPS);
    }
    __syncthreads();
    float mean = sstat[0], rstd = sstat[1];
    for (int i = tid; i < 64 * HW; i += 256) {
        int c = i / HW;
        int cg = g * 64 + c;
        float yn = (sy_[i] - mean) * rstd * sc[cg] + bi[cg];
        out[base + i] = 1.f / (1.f + __expf(-yn));
    }
}

// ---------------- kernel 3: pooled xg (7x7 avg) + per-batch stats ----------
__global__ __launch_bounds__(256) void k_pool(const float* __restrict__ x) {
    __shared__ float sp[HW][HW + 1];
    __shared__ float sah[HW], saw[HW];
    __shared__ float rs_[8], rss_[8];
    int bc = blockIdx.x, tid = threadIdx.x;
    int b = bc >> 8;
    if (tid < HW) { sah[tid] = g_attn_h[bc * HW + tid]; saw[tid] = g_attn_w[bc * HW + tid]; }
    __syncthreads();
    const float4* xp = (const float4*)(x + (size_t)bc * HW * HW);
    #pragma unroll
    for (int k = 0; k < 4; ++k) {
        int f = tid + 256 * k;
        if (f < 784) {
            float4 v = xp[f];
            int r = f / 14, c = (f - r * 14) * 4;
            float a = sah[r];
            sp[r][c]     = v.x * a * saw[c];
            sp[r][c + 1] = v.y * a * saw[c + 1];
            sp[r][c + 2] = v.z * a * saw[c + 2];
            sp[r][c + 3] = v.w * a * saw[c + 3];
        }
    }
    __syncthreads();
    // 4 threads per pooled cell
    int cell = tid >> 2, sub = tid & 3;
    int i = cell >> 3, j = cell & 7;
    float sum = 0.f;
    {
        int u = 0, v = sub;
        #pragma unroll
        for (int t = 0; t < 13; ++t) {
            int idx = sub + 4 * t;
            if (idx < 49) sum += sp[POOL * i + u][POOL * j + v];
            v += 4; if (v >= POOL) { v -= POOL; ++u; }
        }
    }
    sum += __shfl_xor_sync(~0u, sum, 1);
    sum += __shfl_xor_sync(~0u, sum, 2);
    float pv = 0.f;
    if (sub == 0) {
        pv = sum * (1.f / 49.f);
        g_pooled[bc * NN + cell] = pv;
    }
    // per-batch sum/sumsq (only sub==0 lanes carry nonzero)
    float s = pv, ss = pv * pv;
    #pragma unroll
    for (int o = 16; o; o >>= 1) { s += __shfl_xor_sync(~0u, s, o); ss += __shfl_xor_sync(~0u, ss, o); }
    int lane = tid & 31, wid = tid >> 5;
    if (lane == 0) { rs_[wid] = s; rss_[wid] = ss; }
    __syncthreads();
    if (tid == 0) {
        float a = 0.f, c2 = 0.f;
        #pragma unroll
        for (int w = 0; w < 8; ++w) { a += rs_[w]; c2 += rss_[w]; }
        atomicAdd(&g_bsum[b], a);
        atomicAdd(&g_bsumsq[b], c2);
    }
}

// ---------------- kernel 4: attention -> channel gate ----------------------
// grid (head=8, batch=32), block 256 = 8 warps, 4 d-rows per warp, lane = e
__global__ __launch_bounds__(256) void k_attn(
    const float* __restrict__ ns, const float* __restrict__ nb,
    const float* __restrict__ qw, const float* __restrict__ kw,
    const float* __restrict__ vw)
{
    __shared__ float xs[HD][NN + 1];
    __shared__ float svbar[HD];
    int h = blockIdx.x, b = blockIdx.y;
    float bs = g_bsum[b], bss = g_bsumsq[b];
    float mu = bs * (1.f / 16384.f);
    float var = bss * (1.f / 16384.f) - mu * mu;
    float rstd = rsqrtf(var + EPS);
    const float* p = g_pooled + ((size_t)b * C + h * HD) * NN;
    int tid = threadIdx.x;
    for (int i = tid; i < HD * NN; i += 256) {
        int e = i >> 6;
        int c = h * HD + e;
        xs[e][i & 63] = (p[i] - mu) * rstd * ns[c] + nb[c];
    }
    __syncthreads();
    if (tid < HD) {
        float s0 = 0.f, s1 = 0.f;
        #pragma unroll
        for (int n = 0; n < NN; n += 2) { s0 += xs[tid][n]; s1 += xs[tid][n + 1]; }
        svbar[tid] = (s0 + s1) * (1.f / 64.f) * vw[h * HD + tid];
    }
    __syncthreads();

    int wi = tid >> 5, lane = tid & 31;
    float xe[NN];
    #pragma unroll
    for (int n = 0; n < NN; ++n) xe[n] = xs[lane][n];
    float kwe = kw[h * HD + lane];
    float vb  = svbar[lane];
    const float scale = 0.17677669529663687f;  // 32^-0.5

    float sarr[4];
    #pragma unroll
    for (int dd = 0; dd < 4; ++dd) {
        int d = wi * 4 + dd;
        float a0 = 0.f, a1 = 0.f, a2 = 0.f, a3 = 0.f;
        #pragma unroll
        for (int n = 0; n < NN; n += 4) {
            a0 = fmaf(xs[d][n],     xe[n],     a0);
            a1 = fmaf(xs[d][n + 1], xe[n + 1], a1);
            a2 = fmaf(xs[d][n + 2], xe[n + 2], a2);
            a3 = fmaf(xs[d][n + 3], xe[n + 3], a3);
        }
        sarr[dd] = ((a0 + a1) + (a2 + a3)) * qw[h * HD + d] * kwe * scale;
    }
    // 4 independent softmax reductions (compiler interleaves for ILP)
    float m[4], pe[4], Z[4], num[4];
    #pragma unroll
    for (int dd = 0; dd < 4; ++dd) m[dd] = sarr[dd];
    #pragma unroll
    for (int o = 16; o; o >>= 1)
        #pragma unroll
        for (int dd = 0; dd < 4; ++dd)
            m[dd] = fmaxf(m[dd], __shfl_xor_sync(~0u, m[dd], o));
    #pragma unroll
    for (int dd = 0; dd < 4; ++dd) {
        pe[dd]  = __expf(sarr[dd] - m[dd]);
        Z[dd]   = pe[dd];
        num[dd] = pe[dd] * vb;
    }
    #pragma unroll
    for (int o = 16; o; o >>= 1)
        #pragma unroll
        for (int dd = 0; dd < 4; ++dd) {
            Z[dd]   += __shfl_xor_sync(~0u, Z[dd], o);
            num[dd] += __shfl_xor_sync(~0u, num[dd], o);
        }
    if (lane == 0) {
        #pragma unroll
        for (int dd = 0; dd < 4; ++dd) {
            int d = wi * 4 + dd;
            g_ca[b * C + h * HD + d] = 1.f / (1.f + __expf(-(num[dd] / Z[dd])));
        }
    }
}

// ---------------- kernel 5: out = ca * x * ah * aw -------------------------
__global__ __launch_bounds__(256) void k_final(const float* __restrict__ x,
                                               float* __restrict__ out) {
    __shared__ float sca[HW], saw[HW];
    int bc = blockIdx.x, tid = threadIdx.x;
    float ca = g_ca[bc];
    if (tid < HW)                     sca[tid] = ca * g_attn_h[bc * HW + tid];
    else if (tid >= 64 && tid < 120)  saw[tid - 64] = g_attn_w[bc * HW + tid - 64];
    __syncthreads();
    const float4* xp = (const float4*)(x + (size_t)bc * HW * HW);
    float4*       op = (float4*)(out + (size_t)bc * HW * HW);
    float4 v[4]; int f[4]; bool valid[4];
    #pragma unroll
    for (int k = 0; k < 4; ++k) {
        f[k] = tid + 256 * k;
        valid[k] = (f[k] < 784);
        if (valid[k]) v[k] = xp[f[k]];
    }
    #pragma unroll
    for (int k = 0; k < 4; ++k) {
        if (valid[k]) {
            int hrow = f[k] / 14;
            int w4   = (f[k] - hrow * 14) * 4;
            float s = sca[hrow];
            float4 o = v[k];
            o.x *= s * saw[w4 + 0];
            o.y *= s * saw[w4 + 1];
            o.z *= s * saw[w4 + 2];
            o.w *= s * saw[w4 + 3];
            op[f[k]] = o;
        }
    }
}

// ---------------- launch ---------------------------------------------------
extern "C" void kernel_launch(void* const* d_in, const int* in_sizes, int n_in,
                              void* d_out, int out_size) {
    const float* x  = (const float*)d_in[0];
    const float* w3 = (const float*)d_in[1];
    const float* b3 = (const float*)d_in[2];
    const float* w5 = (const float*)d_in[3];
    const float* b5 = (const float*)d_in[4];
    const float* w7 = (const float*)d_in[5];
    const float* b7 = (const float*)d_in[6];
    const float* w9 = (const float*)d_in[7];
    const float* b9 = (const float*)d_in[8];
    const float* nhs = (const float*)d_in[9];
    const float* nhb = (const float*)d_in[10];
    const float* nws = (const float*)d_in[11];
    const float* nwb = (const float*)d_in[12];
    const float* ns  = (const float*)d_in[13];
    const float* nb  = (const float*)d_in[14];
    const float* qw  = (const float*)d_in[15];
    const float* kw  = (const float*)d_in[16];
    const float* vw  = (const float*)d_in[17];
    float* out = (float*)d_out;

    k_means<<<BC, 256>>>(x);
    k_sa<<<dim3(4, B, 2), 256>>>(w3, b3, w5, b5, w7, b7, w9, b9, nhs, nhb, nws, nwb);
    k_pool<<<BC, 256>>>(x);
    k_attn<<<dim3(HEADS, B), 256>>>(ns, nb, qw, kw, vw);
    k_final<<<BC, 256>>>(x, out);
}

// round 4
// speedup vs baseline: 1.4725x; 1.4725x over previous
#include <cuda_runtime.h>
#include <math.h>

#define B 32
#define C 256
#define HW 56
#define BC (B*C)
#define POOL 7
#define NN 64
#define HEADS 8
#define HD 32
#define EPS 1e-5f

// ---------------- scratch ----------------
__device__ float g_mean_h[BC * HW];
__device__ float g_mean_w[BC * HW];
__device__ float g_attn_h[BC * HW];
__device__ float g_attn_w[BC * HW];
__device__ float g_pooled[BC * NN];
__device__ float g_bsum[B];
__device__ float g_bsumsq[B];
__device__ float g_ca[BC];

// ---------------- kernel 1: row & col means (R2 version) -------------------
__global__ __launch_bounds__(256) void k_means(const float* __restrict__ x) {
    __shared__ float sp[HW][HW + 1];
    int bc = blockIdx.x, tid = threadIdx.x;
    if (tid == 0 && bc < B) { g_bsum[bc] = 0.f; g_bsumsq[bc] = 0.f; }
    const float4* xp = (const float4*)(x + (size_t)bc * HW * HW);
    #pragma unroll
    for (int k = 0; k < 4; ++k) {
        int f = tid + 256 * k;
        if (f < 784) {
            float4 v = xp[f];
            int r = f / 14, c = (f - r * 14) * 4;
            sp[r][c]     = v.x;
            sp[r][c + 1] = v.y;
            sp[r][c + 2] = v.z;
            sp[r][c + 3] = v.w;
        }
    }
    __syncthreads();
    if (tid < HW) {
        float rs = 0.f, cs = 0.f;
        #pragma unroll
        for (int w = 0; w < HW; ++w) { rs += sp[tid][w]; cs += sp[w][tid]; }
        g_mean_h[bc * HW + tid] = rs * (1.f / 56.f);
        g_mean_w[bc * HW + tid] = cs * (1.f / 56.f);
    }
}

// ---------------- kernel 2: sa_branch (dwconv -> GN(4) -> sigmoid) ---------
__global__ __launch_bounds__(256) void k_sa(
    const float* __restrict__ w3, const float* __restrict__ b3,
    const float* __restrict__ w5, const float* __restrict__ b5,
    const float* __restrict__ w7, const float* __restrict__ b7,
    const float* __restrict__ w9, const float* __restrict__ b9,
    const float* __restrict__ sh, const float* __restrict__ bh,
    const float* __restrict__ sw, const float* __restrict__ bw)
{
    __shared__ float sin_[64 * HW];
    __shared__ float sy_[64 * HW];
    __shared__ float r1[8], r2[8], sstat[2];

    int g  = blockIdx.x;
    int b  = blockIdx.y;
    int br = blockIdx.z;
    const float* in  = (br == 0) ? g_mean_h : g_mean_w;
    float*       out = (br == 0) ? g_attn_h : g_attn_w;
    const float* sc  = (br == 0) ? sh : sw;
    const float* bi  = (br == 0) ? bh : bw;
    const float* wf; const float* bf; int ksz;
    if (g == 0)      { wf = w3; bf = b3; ksz = 3; }
    else if (g == 1) { wf = w5; bf = b5; ksz = 5; }
    else if (g == 2) { wf = w7; bf = b7; ksz = 7; }
    else             { wf = w9; bf = b9; ksz = 9; }
    int pad = ksz >> 1;

    int tid = threadIdx.x;
    size_t base = ((size_t)b * C + g * 64) * HW;
    for (int i = tid; i < 64 * HW; i += 256) sin_[i] = in[base + i];
    __syncthreads();

    float s = 0.f, ss = 0.f;
    for (int i = tid; i < 64 * HW; i += 256) {
        int c = i / HW, l = i - c * HW;
        float acc = bf[c];
        for (int j = 0; j < ksz; ++j) {
            int idx = l + j - pad;
            if (idx >= 0 && idx < HW) acc = fmaf(wf[c * ksz + j], sin_[c * HW + idx], acc);
        }
        sy_[i] = acc;
        s += acc; ss = fmaf(acc, acc, ss);
    }
    int lane = tid & 31, wid = tid >> 5;
    #pragma unroll
    for (int o = 16; o; o >>= 1) { s += __shfl_xor_sync(~0u, s, o); ss += __shfl_xor_sync(~0u, ss, o); }
    if (lane == 0) { r1[wid] = s; r2[wid] = ss; }
    __syncthreads();
    if (tid == 0) {
        float a = 0.f, bsum = 0.f;
        #pragma unroll
        for (int w = 0; w < 8; ++w) { a += r1[w]; bsum += r2[w]; }
        float mean = a * (1.f / 3584.f);
        float var  = bsum * (1.f / 3584.f) - mean * mean;
        sstat[0] = mean;
        sstat[1] = rsqrtf(var + EPS);
    }
    __syncthreads();
    float mean = sstat[0], rstd = sstat[1];
    for (int i = tid; i < 64 * HW; i += 256) {
        int c = i / HW;
        int cg = g * 64 + c;
        float yn = (sy_[i] - mean) * rstd * sc[cg] + bi[cg];
        out[base + i] = 1.f / (1.f + __expf(-yn));
    }
}

// ---------------- kernel 3: pooled xg + per-batch stats (R2 version) -------
__global__ __launch_bounds__(256) void k_pool(const float* __restrict__ x) {
    __shared__ float sp[HW][HW + 1];
    __shared__ float sah[HW], saw[HW];
    __shared__ float rs_[2], rss_[2];
    int bc = blockIdx.x, tid = threadIdx.x;
    int b = bc >> 8;
    if (tid < HW) { sah[tid] = g_attn_h[bc * HW + tid]; saw[tid] = g_attn_w[bc * HW + tid]; }
    __syncthreads();
    const float4* xp = (const float4*)(x + (size_t)bc * HW * HW);
    #pragma unroll
    for (int k = 0; k < 4; ++k) {
        int f = tid + 256 * k;
        if (f < 784) {
            float4 v = xp[f];
            int r = f / 14, c = (f - r * 14) * 4;
            float a = sah[r];
            sp[r][c]     = v.x * a * saw[c];
            sp[r][c + 1] = v.y * a * saw[c + 1];
            sp[r][c + 2] = v.z * a * saw[c + 2];
            sp[r][c + 3] = v.w * a * saw[c + 3];
        }
    }
    __syncthreads();
    float pv = 0.f;
    if (tid < NN) {
        int i = tid >> 3, j = tid & 7;
        float sum = 0.f;
        #pragma unroll
        for (int u = 0; u < POOL; ++u)
            #pragma unroll
            for (int v = 0; v < POOL; ++v)
                sum += sp[POOL * i + u][POOL * j + v];
        pv = sum * (1.f / 49.f);
        g_pooled[bc * NN + tid] = pv;
    }
    if (tid < NN) {
        float s = pv, ss = pv * pv;
        #pragma unroll
        for (int o = 16; o; o >>= 1) { s += __shfl_xor_sync(~0u, s, o); ss += __shfl_xor_sync(~0u, ss, o); }
        int lane = tid & 31, wid = tid >> 5;
        if (lane == 0) { rs_[wid] = s; rss_[wid] = ss; }
    }
    __syncthreads();
    if (tid == 0) {
        atomicAdd(&g_bsum[b],   rs_[0] + rs_[1]);
        atomicAdd(&g_bsumsq[b], rss_[0] + rss_[1]);
    }
}

// ---------------- kernel 4: attention -> channel gate ----------------------
// grid (head=8, batch=32), block 256 = 8 warps, 4 d-rows/warp, lane = e.
// NO per-thread key cache (caused local-memory spills); both dot operands
// come from shared: xs[lane][n] conflict-free (stride 65), xs[d][n] broadcast.
__global__ __launch_bounds__(256) void k_attn(
    const float* __restrict__ ns, const float* __restrict__ nb,
    const float* __restrict__ qw, const float* __restrict__ kw,
    const float* __restrict__ vw)
{
    __shared__ float xs[HD][NN + 1];
    __shared__ float svbar[HD];
    int h = blockIdx.x, b = blockIdx.y;
    float bs = g_bsum[b], bss = g_bsumsq[b];
    float mu = bs * (1.f / 16384.f);
    float var = bss * (1.f / 16384.f) - mu * mu;
    float rstd = rsqrtf(var + EPS);
    const float* p = g_pooled + ((size_t)b * C + h * HD) * NN;
    int tid = threadIdx.x;
    for (int i = tid; i < HD * NN; i += 256) {
        int e = i >> 6;
        int c = h * HD + e;
        xs[e][i & 63] = (p[i] - mu) * rstd * ns[c] + nb[c];
    }
    __syncthreads();
    if (tid < HD) {
        float s0 = 0.f, s1 = 0.f;
        #pragma unroll
        for (int n = 0; n < NN; n += 2) { s0 += xs[tid][n]; s1 += xs[tid][n + 1]; }
        svbar[tid] = (s0 + s1) * (1.f / 64.f) * vw[h * HD + tid];
    }
    __syncthreads();

    int wi = tid >> 5, lane = tid & 31;
    float kwe = kw[h * HD + lane];
    float vb  = svbar[lane];
    const float scale = 0.17677669529663687f;  // 32^-0.5

    int d0 = wi * 4;
    float acc0[4], acc1[4];
    #pragma unroll
    for (int dd = 0; dd < 4; ++dd) { acc0[dd] = 0.f; acc1[dd] = 0.f; }
    #pragma unroll
    for (int n = 0; n < NN; n += 2) {
        float t0 = xs[lane][n];       // conflict-free across lanes
        float t1 = xs[lane][n + 1];
        #pragma unroll
        for (int dd = 0; dd < 4; ++dd) {
            acc0[dd] = fmaf(xs[d0 + dd][n],     t0, acc0[dd]);  // broadcast
            acc1[dd] = fmaf(xs[d0 + dd][n + 1], t1, acc1[dd]);
        }
    }
    float sarr[4];
    #pragma unroll
    for (int dd = 0; dd < 4; ++dd)
        sarr[dd] = (acc0[dd] + acc1[dd]) * qw[h * HD + d0 + dd] * kwe * scale;

    float m[4], pe[4], Z[4], num[4];
    #pragma unroll
    for (int dd = 0; dd < 4; ++dd) m[dd] = sarr[dd];
    #pragma unroll
    for (int o = 16; o; o >>= 1)
        #pragma unroll
        for (int dd = 0; dd < 4; ++dd)
            m[dd] = fmaxf(m[dd], __shfl_xor_sync(~0u, m[dd], o));
    #pragma unroll
    for (int dd = 0; dd < 4; ++dd) {
        pe[dd]  = __expf(sarr[dd] - m[dd]);
        Z[dd]   = pe[dd];
        num[dd] = pe[dd] * vb;
    }
    #pragma unroll
    for (int o = 16; o; o >>= 1)
        #pragma unroll
        for (int dd = 0; dd < 4; ++dd) {
            Z[dd]   += __shfl_xor_sync(~0u, Z[dd], o);
            num[dd] += __shfl_xor_sync(~0u, num[dd], o);
        }
    if (lane == 0) {
        #pragma unroll
        for (int dd = 0; dd < 4; ++dd)
            g_ca[b * C + h * HD + d0 + dd] = 1.f / (1.f + __expf(-(num[dd] / Z[dd])));
    }
}

// ---------------- kernel 5: out = ca * x * ah * aw -------------------------
__global__ __launch_bounds__(256) void k_final(const float* __restrict__ x,
                                               float* __restrict__ out) {
    __shared__ float sca[HW], saw[HW];
    int bc = blockIdx.x, tid = threadIdx.x;
    float ca = g_ca[bc];
    if (tid < HW)                     sca[tid] = ca * g_attn_h[bc * HW + tid];
    else if (tid >= 64 && tid < 120)  saw[tid - 64] = g_attn_w[bc * HW + tid - 64];
    __syncthreads();
    const float4* xp = (const float4*)(x + (size_t)bc * HW * HW);
    float4*       op = (float4*)(out + (size_t)bc * HW * HW);
    float4 v[4]; int f[4]; bool valid[4];
    #pragma unroll
    for (int k = 0; k < 4; ++k) {
        f[k] = tid + 256 * k;
        valid[k] = (f[k] < 784);
        if (valid[k]) v[k] = xp[f[k]];
    }
    #pragma unroll
    for (int k = 0; k < 4; ++k) {
        if (valid[k]) {
            int hrow = f[k] / 14;
            int w4   = (f[k] - hrow * 14) * 4;
            float s = sca[hrow];
            float4 o = v[k];
            o.x *= s * saw[w4 + 0];
            o.y *= s * saw[w4 + 1];
            o.z *= s * saw[w4 + 2];
            o.w *= s * saw[w4 + 3];
            op[f[k]] = o;
        }
    }
}

// ---------------- launch ---------------------------------------------------
extern "C" void kernel_launch(void* const* d_in, const int* in_sizes, int n_in,
                              void* d_out, int out_size) {
    const float* x  = (const float*)d_in[0];
    const float* w3 = (const float*)d_in[1];
    const float* b3 = (const float*)d_in[2];
    const float* w5 = (const float*)d_in[3];
    const float* b5 = (const float*)d_in[4];
    const float* w7 = (const float*)d_in[5];
    const float* b7 = (const float*)d_in[6];
    const float* w9 = (const float*)d_in[7];
    const float* b9 = (const float*)d_in[8];
    const float* nhs = (const float*)d_in[9];
    const float* nhb = (const float*)d_in[10];
    const float* nws = (const float*)d_in[11];
    const float* nwb = (const float*)d_in[12];
    const float* ns  = (const float*)d_in[13];
    const float* nb  = (const float*)d_in[14];
    const float* qw  = (const float*)d_in[15];
    const float* kw  = (const float*)d_in[16];
    const float* vw  = (const float*)d_in[17];
    float* out = (float*)d_out;

    k_means<<<BC, 256>>>(x);
    k_sa<<<dim3(4, B, 2), 256>>>(w3, b3, w5, b5, w7, b7, w9, b9, nhs, nhb, nws, nwb);
    k_pool<<<BC, 256>>>(x);
    k_attn<<<dim3(HEADS, B), 256>>>(ns, nb, qw, kw, vw);
    k_final<<<BC, 256>>>(x, out);
}

// round 5
// speedup vs baseline: 1.5991x; 1.0860x over previous
#include <cuda_runtime.h>
#include <math.h>

#define B 32
#define C 256
#define HW 56
#define BC (B*C)
#define POOL 7
#define NN 64
#define HEADS 8
#define HD 32
#define EPS 1e-5f

// ---------------- scratch ----------------
__device__ float g_mean_h[BC * HW];
__device__ float g_mean_w[BC * HW];
__device__ float g_attn_h[BC * HW];
__device__ float g_attn_w[BC * HW];
__device__ float g_pooled[BC * NN];
__device__ float g_bsum[B];
__device__ float g_bsumsq[B];
__device__ float g_ca[BC];

// ---------------- kernel 1: row & col means of each 56x56 plane ------------
__global__ __launch_bounds__(256) void k_means(const float* __restrict__ x) {
    __shared__ float sp[HW][HW + 1];
    int bc = blockIdx.x, tid = threadIdx.x;
    if (tid == 0 && bc < B) { g_bsum[bc] = 0.f; g_bsumsq[bc] = 0.f; }
    const float4* xp = (const float4*)(x + (size_t)bc * HW * HW);
    #pragma unroll
    for (int k = 0; k < 4; ++k) {
        int f = tid + 256 * k;
        if (f < 784) {
            float4 v = xp[f];
            int r = f / 14, c = (f - r * 14) * 4;
            sp[r][c]     = v.x;
            sp[r][c + 1] = v.y;
            sp[r][c + 2] = v.z;
            sp[r][c + 3] = v.w;
        }
    }
    __syncthreads();
    if (tid < HW) {
        float rs = 0.f, cs = 0.f;
        #pragma unroll
        for (int w = 0; w < HW; ++w) { rs += sp[tid][w]; cs += sp[w][tid]; }
        g_mean_h[bc * HW + tid] = rs * (1.f / 56.f);
        g_mean_w[bc * HW + tid] = cs * (1.f / 56.f);
    }
}

// ---------------- kernel 2: sa_branch (dwconv -> GN(4) -> sigmoid) ---------
// grid (group=4, batch=32, branch=2), block 512. float4 I/O, conv in regs.
__global__ __launch_bounds__(512) void k_sa(
    const float* __restrict__ w3, const float* __restrict__ b3,
    const float* __restrict__ w5, const float* __restrict__ b5,
    const float* __restrict__ w7, const float* __restrict__ b7,
    const float* __restrict__ w9, const float* __restrict__ b9,
    const float* __restrict__ sh, const float* __restrict__ bh,
    const float* __restrict__ sw, const float* __restrict__ bw)
{
    __shared__ __align__(16) float sin_[64 * HW];   // 3584 floats
    __shared__ float r1[16], r2[16], sstat[2];

    int g  = blockIdx.x;
    int b  = blockIdx.y;
    int br = blockIdx.z;
    const float* in  = (br == 0) ? g_mean_h : g_mean_w;
    float*       out = (br == 0) ? g_attn_h : g_attn_w;
    const float* sc  = (br == 0) ? sh : sw;
    const float* bi  = (br == 0) ? bh : bw;
    const float* wf; const float* bf; int ksz;
    if (g == 0)      { wf = w3; bf = b3; ksz = 3; }
    else if (g == 1) { wf = w5; bf = b5; ksz = 5; }
    else if (g == 2) { wf = w7; bf = b7; ksz = 7; }
    else             { wf = w9; bf = b9; ksz = 9; }
    int pad = ksz >> 1;

    int tid = threadIdx.x;
    size_t base = ((size_t)b * C + g * 64) * HW;     // multiple of 3584 -> 16B aligned
    const float4* in4 = (const float4*)(in + base);
    float4*       out4 = (float4*)(out + base);
    #pragma unroll
    for (int k = 0; k < 2; ++k) {
        int f = tid + 512 * k;
        if (f < 896) ((float4*)sin_)[f] = in4[f];
    }
    __syncthreads();

    // conv: 2 float4 (8 outputs) per thread, kept in registers
    float o[8];
    float s = 0.f, ss = 0.f;
    int   cch[2];
    #pragma unroll
    for (int k = 0; k < 2; ++k) {
        int f = tid + 512 * k;
        if (f < 896) {
            int c  = f / 14;
            int l0 = (f - c * 14) * 4;
            cch[k] = c;
            const float* row = sin_ + c * HW;
            #pragma unroll
            for (int q = 0; q < 4; ++q) {
                int l = l0 + q;
                float acc = bf[c];
                for (int j = 0; j < ksz; ++j) {
                    int idx = l + j - pad;
                    if (idx >= 0 && idx < HW) acc = fmaf(wf[c * ksz + j], row[idx], acc);
                }
                o[k * 4 + q] = acc;
                s += acc; ss = fmaf(acc, acc, ss);
            }
        } else cch[k] = -1;
    }
    int lane = tid & 31, wid = tid >> 5;
    #pragma unroll
    for (int off = 16; off; off >>= 1) { s += __shfl_xor_sync(~0u, s, off); ss += __shfl_xor_sync(~0u, ss, off); }
    if (lane == 0) { r1[wid] = s; r2[wid] = ss; }
    __syncthreads();
    if (tid == 0) {
        float a = 0.f, bs2 = 0.f;
        #pragma unroll
        for (int w = 0; w < 16; ++w) { a += r1[w]; bs2 += r2[w]; }
        float mean = a * (1.f / 3584.f);
        float var  = bs2 * (1.f / 3584.f) - mean * mean;
        sstat[0] = mean;
        sstat[1] = rsqrtf(var + EPS);
    }
    __syncthreads();
    float mean = sstat[0], rstd = sstat[1];
    #pragma unroll
    for (int k = 0; k < 2; ++k) {
        if (cch[k] >= 0) {
            int f = tid + 512 * k;
            int cg = g * 64 + cch[k];
            float a_ = rstd * sc[cg], b_ = bi[cg] - mean * a_;
            float4 v;
            v.x = 1.f / (1.f + __expf(-(o[k*4+0] * a_ + b_)));
            v.y = 1.f / (1.f + __expf(-(o[k*4+1] * a_ + b_)));
            v.z = 1.f / (1.f + __expf(-(o[k*4+2] * a_ + b_)));
            v.w = 1.f / (1.f + __expf(-(o[k*4+3] * a_ + b_)));
            out4[f] = v;
        }
    }
}

// ---------------- kernel 3: pooled xg + per-batch stats --------------------
__global__ __launch_bounds__(256) void k_pool(const float* __restrict__ x) {
    __shared__ float sp[HW][HW + 1];
    __shared__ float sah[HW], saw[HW];
    __shared__ float rs_[2], rss_[2];
    int bc = blockIdx.x, tid = threadIdx.x;
    int b = bc >> 8;
    if (tid < HW) { sah[tid] = g_attn_h[bc * HW + tid]; saw[tid] = g_attn_w[bc * HW + tid]; }
    __syncthreads();
    const float4* xp = (const float4*)(x + (size_t)bc * HW * HW);
    #pragma unroll
    for (int k = 0; k < 4; ++k) {
        int f = tid + 256 * k;
        if (f < 784) {
            float4 v = xp[f];
            int r = f / 14, c = (f - r * 14) * 4;
            float a = sah[r];
            sp[r][c]     = v.x * a * saw[c];
            sp[r][c + 1] = v.y * a * saw[c + 1];
            sp[r][c + 2] = v.z * a * saw[c + 2];
            sp[r][c + 3] = v.w * a * saw[c + 3];
        }
    }
    __syncthreads();
    float pv = 0.f;
    if (tid < NN) {
        int i = tid >> 3, j = tid & 7;
        float sum = 0.f;
        #pragma unroll
        for (int u = 0; u < POOL; ++u)
            #pragma unroll
            for (int v = 0; v < POOL; ++v)
                sum += sp[POOL * i + u][POOL * j + v];
        pv = sum * (1.f / 49.f);
        g_pooled[bc * NN + tid] = pv;
    }
    if (tid < NN) {
        float s = pv, ss = pv * pv;
        #pragma unroll
        for (int o = 16; o; o >>= 1) { s += __shfl_xor_sync(~0u, s, o); ss += __shfl_xor_sync(~0u, ss, o); }
        int lane = tid & 31, wid = tid >> 5;
        if (lane == 0) { rs_[wid] = s; rss_[wid] = ss; }
    }
    __syncthreads();
    if (tid == 0) {
        atomicAdd(&g_bsum[b],   rs_[0] + rs_[1]);
        atomicAdd(&g_bsumsq[b], rss_[0] + rss_[1]);
    }
}

// ---------------- kernel 4: attention -> channel gate ----------------------
// grid (head=8, batch=32), block 256. Row stride 68 floats (17 float4):
// 17*l mod 8 == l mod 8 -> conflict-free LDS.128 across lanes; 16B aligned.
__global__ __launch_bounds__(256) void k_attn(
    const float* __restrict__ ns, const float* __restrict__ nb,
    const float* __restrict__ qw, const float* __restrict__ kw,
    const float* __restrict__ vw)
{
    __shared__ __align__(16) float xs[HD * 68];
    __shared__ float svbar[HD];
    int h = blockIdx.x, b = blockIdx.y;
    float bs = g_bsum[b], bss = g_bsumsq[b];
    float mu = bs * (1.f / 16384.f);
    float var = bss * (1.f / 16384.f) - mu * mu;
    float rstd = rsqrtf(var + EPS);
    const float4* p4 = (const float4*)(g_pooled + ((size_t)b * C + h * HD) * NN);
    int tid = threadIdx.x;
    #pragma unroll
    for (int k = 0; k < 2; ++k) {
        int f = tid + 256 * k;            // 0..511
        float4 v = p4[f];
        int e = f >> 4;                    // 16 float4 per row
        int c = h * HD + e;
        float a_ = rstd * ns[c], b_ = nb[c] - mu * a_;
        v.x = v.x * a_ + b_;
        v.y = v.y * a_ + b_;
        v.z = v.z * a_ + b_;
        v.w = v.w * a_ + b_;
        ((float4*)xs)[e * 17 + (f & 15)] = v;
    }
    __syncthreads();

    int wi = tid >> 5, lane = tid & 31;
    // vbar: each warp handles rows wi*4..wi*4+3 (shuffle reduce, interleaved)
    {
        float sv[4];
        #pragma unroll
        for (int dd = 0; dd < 4; ++dd) {
            int row = wi * 4 + dd;
            sv[dd] = xs[row * 68 + lane] + xs[row * 68 + lane + 32];
        }
        #pragma unroll
        for (int o = 16; o; o >>= 1)
            #pragma unroll
            for (int dd = 0; dd < 4; ++dd)
                sv[dd] += __shfl_xor_sync(~0u, sv[dd], o);
        if (lane == 0) {
            #pragma unroll
            for (int dd = 0; dd < 4; ++dd) {
                int row = wi * 4 + dd;
                svbar[row] = sv[dd] * (1.f / 64.f) * vw[h * HD + row];
            }
        }
    }
    __syncthreads();

    float kwe = kw[h * HD + lane];
    float vb  = svbar[lane];
    const float scale = 0.17677669529663687f;  // 32^-0.5
    int d0 = wi * 4;
    const float4* xs4 = (const float4*)xs;

    float acc[4];
    #pragma unroll
    for (int dd = 0; dd < 4; ++dd) acc[dd] = 0.f;
    #pragma unroll
    for (int j = 0; j < 16; ++j) {
        float4 t = xs4[lane * 17 + j];          // conflict-free LDS.128
        #pragma unroll
        for (int dd = 0; dd < 4; ++dd) {
            float4 q = xs4[(d0 + dd) * 17 + j]; // broadcast LDS.128
            acc[dd] = fmaf(t.x, q.x, acc[dd]);
            acc[dd] = fmaf(t.y, q.y, acc[dd]);
            acc[dd] = fmaf(t.z, q.z, acc[dd]);
            acc[dd] = fmaf(t.w, q.w, acc[dd]);
        }
    }
    float sarr[4];
    #pragma unroll
    for (int dd = 0; dd < 4; ++dd)
        sarr[dd] = acc[dd] * qw[h * HD + d0 + dd] * kwe * scale;

    float m[4], pe[4], Z[4], num[4];
    #pragma unroll
    for (int dd = 0; dd < 4; ++dd) m[dd] = sarr[dd];
    #pragma unroll
    for (int o = 16; o; o >>= 1)
        #pragma unroll
        for (int dd = 0; dd < 4; ++dd)
            m[dd] = fmaxf(m[dd], __shfl_xor_sync(~0u, m[dd], o));
    #pragma unroll
    for (int dd = 0; dd < 4; ++dd) {
        pe[dd]  = __expf(sarr[dd] - m[dd]);
        Z[dd]   = pe[dd];
        num[dd] = pe[dd] * vb;
    }
    #pragma unroll
    for (int o = 16; o; o >>= 1)
        #pragma unroll
        for (int dd = 0; dd < 4; ++dd) {
            Z[dd]   += __shfl_xor_sync(~0u, Z[dd], o);
            num[dd] += __shfl_xor_sync(~0u, num[dd], o);
        }
    if (lane == 0) {
        #pragma unroll
        for (int dd = 0; dd < 4; ++dd)
            g_ca[b * C + h * HD + d0 + dd] = 1.f / (1.f + __expf(-(num[dd] / Z[dd])));
    }
}

// ---------------- kernel 5: out = ca * x * ah * aw -------------------------
__global__ __launch_bounds__(256) void k_final(const float* __restrict__ x,
                                               float* __restrict__ out) {
    __shared__ float sca[HW], saw[HW];
    int bc = blockIdx.x, tid = threadIdx.x;
    float ca = g_ca[bc];
    if (tid < HW)                     sca[tid] = ca * g_attn_h[bc * HW + tid];
    else if (tid >= 64 && tid < 120)  saw[tid - 64] = g_attn_w[bc * HW + tid - 64];
    __syncthreads();
    const float4* xp = (const float4*)(x + (size_t)bc * HW * HW);
    float4*       op = (float4*)(out + (size_t)bc * HW * HW);
    float4 v[4]; int f[4]; bool valid[4];
    #pragma unroll
    for (int k = 0; k < 4; ++k) {
        f[k] = tid + 256 * k;
        valid[k] = (f[k] < 784);
        if (valid[k]) v[k] = xp[f[k]];
    }
    #pragma unroll
    for (int k = 0; k < 4; ++k) {
        if (valid[k]) {
            int hrow = f[k] / 14;
            int w4   = (f[k] - hrow * 14) * 4;
            float s = sca[hrow];
            float4 o = v[k];
            o.x *= s * saw[w4 + 0];
            o.y *= s * saw[w4 + 1];
            o.z *= s * saw[w4 + 2];
            o.w *= s * saw[w4 + 3];
            op[f[k]] = o;
        }
    }
}

// ---------------- launch ---------------------------------------------------
extern "C" void kernel_launch(void* const* d_in, const int* in_sizes, int n_in,
                              void* d_out, int out_size) {
    const float* x  = (const float*)d_in[0];
    const float* w3 = (const float*)d_in[1];
    const float* b3 = (const float*)d_in[2];
    const float* w5 = (const float*)d_in[3];
    const float* b5 = (const float*)d_in[4];
    const float* w7 = (const float*)d_in[5];
    const float* b7 = (const float*)d_in[6];
    const float* w9 = (const float*)d_in[7];
    const float* b9 = (const float*)d_in[8];
    const float* nhs = (const float*)d_in[9];
    const float* nhb = (const float*)d_in[10];
    const float* nws = (const float*)d_in[11];
    const float* nwb = (const float*)d_in[12];
    const float* ns  = (const float*)d_in[13];
    const float* nb  = (const float*)d_in[14];
    const float* qw  = (const float*)d_in[15];
    const float* kw  = (const float*)d_in[16];
    const float* vw  = (const float*)d_in[17];
    float* out = (float*)d_out;

    k_means<<<BC, 256>>>(x);
    k_sa<<<dim3(4, B, 2), 512>>>(w3, b3, w5, b5, w7, b7, w9, b9, nhs, nhb, nws, nwb);
    k_pool<<<BC, 256>>>(x);
    k_attn<<<dim3(HEADS, B), 256>>>(ns, nb, qw, kw, vw);
    k_final<<<BC, 256>>>(x, out);
}